// round 4
// baseline (speedup 1.0000x reference)
#include <cuda_runtime.h>

// Fully-fused 4-level 2D Haar DWT — single-wave version.
// Input x: (32, 3, 512, 512) fp32.
// Output: concat of t1 (32,12,256,256), t2 (32,12,128,128),
//         t3 (32,12,64,64), t4 (32,12,32,32).
// One block = one 128x128 input tile of one (batch,color) plane.
// No smem: level k+1 re-reads level k's LL band from d_out (guaranteed L2-hot,
// written by this same block; __syncthreads orders global visibility).
// 128-thread blocks, min 12 blocks/SM -> all 1536 blocks fit in ONE wave.
// Level 4 computes r,g only (b4 = g4 duplicated into channels 8..11).

#define HAAR(a_, b_, c_, d_, LL, LH, HL, HH)      \
    do {                                          \
        float L0 = (a_ + c_) * 0.5f;              \
        float L1 = (b_ + d_) * 0.5f;              \
        float H0 = fabsf(a_ - c_);                \
        float H1 = fabsf(b_ - d_);                \
        LL = (L0 + L1) * 0.5f;                    \
        LH = fabsf(L0 - L1);                      \
        HL = (H0 + H1) * 0.5f;                    \
        HH = fabsf(H0 - H1);                      \
    } while (0)

__global__ __launch_bounds__(128, 12) void dwt_fused_kernel(
    const float* __restrict__ x, float* __restrict__ out)
{
    const int tid = threadIdx.x;
    const int tj  = blockIdx.x;       // 0..3 (col tile)
    const int ti  = blockIdx.y;       // 0..3 (row tile)
    const int bc  = blockIdx.z;       // 0..95
    const int b   = bc / 3;
    const int c   = bc % 3;

    const long S1 = 32L * 12 * 256 * 256;
    const long S2 = 32L * 12 * 128 * 128;
    const long S3 = 32L * 12 * 64 * 64;

    // Per-block output region bases
    float* o1 = out + (long)b * (12 * 65536) + (long)(c * 4) * 65536
                    + (long)(ti * 64) * 256 + tj * 64;
    float* o2 = out + S1 + (long)b * (12 * 16384) + (long)(c * 4) * 16384
                    + (long)(ti * 32) * 128 + tj * 32;
    float* o3 = out + S1 + S2 + (long)b * (12 * 4096) + (long)(c * 4) * 4096
                    + (long)(ti * 16) * 64 + tj * 16;
    float* o4 = out + S1 + S2 + S3 + (long)b * (12 * 1024) + (long)(c * 4) * 1024
                    + (long)(ti * 8) * 32 + tj * 8;

    // ---- Level 1: x -> t1.  64x64 outputs, 32 px/thread ------------------
    {
        const float* ip = x + (long)b * (3 * 512 * 512)
                            + (long)c * (512 * 512)
                            + (long)(ti * 128) * 512 + tj * 128;

        const int col  = tid & 63;     // output col 0..63
        const int row0 = tid >> 6;     // 0..1

        #pragma unroll 4
        for (int r = row0; r < 64; r += 2) {
            const float2* r0 = reinterpret_cast<const float2*>(ip + (long)(2 * r) * 512);
            const float2* r1 = reinterpret_cast<const float2*>(ip + (long)(2 * r + 1) * 512);
            float2 t = __ldcs(&r0[col]);
            float2 u = __ldcs(&r1[col]);

            float LL, LH, HL, HH;
            HAAR(t.x, t.y, u.x, u.y, LL, LH, HL, HH);

            float* orow = o1 + (long)r * 256 + col;
            orow[0] = LL;                         // re-read by level 2: keep cached
            __stcs(orow + 65536,     LH);
            __stcs(orow + 2 * 65536, HL);
            __stcs(orow + 3 * 65536, HH);
        }
    }
    __syncthreads();

    // ---- Level 2: t1-LL (o1 region) -> t2.  32x32 outputs, 8 px/thread ---
    {
        const int col  = tid & 31;     // 0..31
        const int row0 = tid >> 5;     // 0..3

        #pragma unroll
        for (int r = row0; r < 32; r += 4) {
            const float2* r0 = reinterpret_cast<const float2*>(o1 + (long)(2 * r) * 256);
            const float2* r1 = reinterpret_cast<const float2*>(o1 + (long)(2 * r + 1) * 256);
            float2 t = r0[col];
            float2 u = r1[col];

            float LL, LH, HL, HH;
            HAAR(t.x, t.y, u.x, u.y, LL, LH, HL, HH);

            float* orow = o2 + (long)r * 128 + col;
            orow[0] = LL;
            __stcs(orow + 16384,     LH);
            __stcs(orow + 2 * 16384, HL);
            __stcs(orow + 3 * 16384, HH);
        }
    }
    __syncthreads();

    // ---- Level 3: t2-LL (o2 region) -> t3.  16x16 outputs, 2 px/thread ---
    {
        const int col  = tid & 15;     // 0..15
        const int row0 = tid >> 4;     // 0..7

        #pragma unroll
        for (int r = row0; r < 16; r += 8) {
            const float2* r0 = reinterpret_cast<const float2*>(o2 + (long)(2 * r) * 128);
            const float2* r1 = reinterpret_cast<const float2*>(o2 + (long)(2 * r + 1) * 128);
            float2 t = r0[col];
            float2 u = r1[col];

            float LL, LH, HL, HH;
            HAAR(t.x, t.y, u.x, u.y, LL, LH, HL, HH);

            float* orow = o3 + (long)r * 64 + col;
            orow[0] = LL;
            __stcs(orow + 4096,     LH);
            __stcs(orow + 2 * 4096, HL);
            __stcs(orow + 3 * 4096, HH);
        }
    }
    __syncthreads();

    // ---- Level 4: t3-LL (o3 region) -> t4.  8x8 outputs, r/g only --------
    if (tid < 64 && c < 2) {
        const int col = tid & 7;       // 0..7
        const int r   = tid >> 3;      // 0..7

        const float2* r0 = reinterpret_cast<const float2*>(o3 + (long)(2 * r) * 64);
        const float2* r1 = reinterpret_cast<const float2*>(o3 + (long)(2 * r + 1) * 64);
        float2 t = r0[col];
        float2 u = r1[col];

        float LL, LH, HL, HH;
        HAAR(t.x, t.y, u.x, u.y, LL, LH, HL, HH);

        float* orow = o4 + (long)r * 32 + col;
        __stcs(orow,            LL);
        __stcs(orow + 1024,     LH);
        __stcs(orow + 2 * 1024, HL);
        __stcs(orow + 3 * 1024, HH);

        if (c == 1) {   // b4 = g4 -> channels 8..11
            float* orow2 = orow + 4 * 1024;
            __stcs(orow2,            LL);
            __stcs(orow2 + 1024,     LH);
            __stcs(orow2 + 2 * 1024, HL);
            __stcs(orow2 + 3 * 1024, HH);
        }
    }
}

extern "C" void kernel_launch(void* const* d_in, const int* in_sizes, int n_in,
                              void* d_out, int out_size)
{
    const float* x = (const float*)d_in[0];
    float* out = (float*)d_out;

    dim3 block(128, 1, 1);
    dim3 grid(4, 4, 96);
    dwt_fused_kernel<<<grid, block>>>(x, out);
}

// round 5
// speedup vs baseline: 1.0949x; 1.0949x over previous
#include <cuda_runtime.h>

// Fully-fused 4-level 2D Haar DWT — R2 smem-cascade kernel, single-wave grid.
// Input x: (32, 3, 512, 512) fp32.
// Output: concat of t1 (32,12,256,256), t2 (32,12,128,128),
//         t3 (32,12,64,64), t4 (32,12,32,32).
// Each block processes TWO 128x128 input tiles (row tiles ti and ti+2) of one
// (batch,color) plane, cascading LL bands through shared memory.
// grid = 768 blocks <= 888 concurrent (6+/SM at 22KB smem, 256 thr) -> 1 wave.
// Level 4 computes r,g only (b4 = g4 duplicated into channels 8..11).

#define HAAR(a_, b_, c_, d_, LL, LH, HL, HH)      \
    do {                                          \
        float L0 = (a_ + c_) * 0.5f;              \
        float L1 = (b_ + d_) * 0.5f;              \
        float H0 = fabsf(a_ - c_);                \
        float H1 = fabsf(b_ - d_);                \
        LL = (L0 + L1) * 0.5f;                    \
        LH = fabsf(L0 - L1);                      \
        HL = (H0 + H1) * 0.5f;                    \
        HH = fabsf(H0 - H1);                      \
    } while (0)

__global__ __launch_bounds__(256) void dwt_fused_kernel(
    const float* __restrict__ x, float* __restrict__ out)
{
    __shared__ float s1[64 * 64];   // 16 KB, L1 LL
    __shared__ float s2[32 * 32];   //  4 KB, L2 LL
    __shared__ float s3[16 * 16];   //  1 KB, L3 LL

    const int tid = threadIdx.x;
    const int tj  = blockIdx.x;        // 0..3  (column tile)
    const int ti0 = blockIdx.y;        // 0..1  (row tile pair base)
    const int bc  = blockIdx.z;        // 0..95
    const int b   = bc / 3;
    const int c   = bc % 3;

    const long S1 = 32L * 12 * 256 * 256;
    const long S2 = 32L * 12 * 128 * 128;
    const long S3 = 32L * 12 * 64 * 64;

    #pragma unroll
    for (int half = 0; half < 2; half++) {
        const int ti = ti0 + 2 * half;     // row tiles: ti0 and ti0+2

        // ---------------- Level 1: x -> t1 (64x64 outputs) -----------------
        {
            const float* ip = x + (long)b * (3 * 512 * 512)
                                + (long)c * (512 * 512)
                                + (long)(ti * 128) * 512 + tj * 128;
            float* o1 = out + (long)b * (12 * 65536)
                            + (long)(c * 4) * 65536
                            + (long)(ti * 64) * 256 + tj * 64;

            const int tx = tid & 63;       // column 0..63
            const int ty = tid >> 6;       // 0..3

            #pragma unroll
            for (int r = ty; r < 64; r += 4) {
                const float2* r0 = reinterpret_cast<const float2*>(ip + (long)(2 * r) * 512);
                const float2* r1 = reinterpret_cast<const float2*>(ip + (long)(2 * r + 1) * 512);
                float2 t = __ldg(&r0[tx]);
                float2 u = __ldg(&r1[tx]);

                float LL, LH, HL, HH;
                HAAR(t.x, t.y, u.x, u.y, LL, LH, HL, HH);

                float* orow = o1 + (long)r * 256 + tx;
                orow[0]          = LL;
                orow[65536]      = LH;
                orow[2 * 65536]  = HL;
                orow[3 * 65536]  = HH;
                s1[r * 64 + tx]  = LL;
            }
        }
        __syncthreads();

        // ---------------- Level 2: s1 -> t2 (32x32 outputs) ----------------
        {
            float* o2 = out + S1 + (long)b * (12 * 16384)
                            + (long)(c * 4) * 16384
                            + (long)(ti * 32) * 128 + tj * 32;

            const int tx = tid & 31;       // column 0..31
            const int ty = tid >> 5;       // 0..7
            const float2* s1v = reinterpret_cast<const float2*>(s1);

            #pragma unroll
            for (int r = ty; r < 32; r += 8) {
                float2 t = s1v[(2 * r) * 32 + tx];
                float2 u = s1v[(2 * r + 1) * 32 + tx];

                float LL, LH, HL, HH;
                HAAR(t.x, t.y, u.x, u.y, LL, LH, HL, HH);

                float* orow = o2 + (long)r * 128 + tx;
                orow[0]          = LL;
                orow[16384]      = LH;
                orow[2 * 16384]  = HL;
                orow[3 * 16384]  = HH;
                s2[r * 32 + tx]  = LL;
            }
        }
        __syncthreads();

        // ---------------- Level 3: s2 -> t3 (16x16 outputs) ----------------
        {
            float* o3 = out + S1 + S2 + (long)b * (12 * 4096)
                            + (long)(c * 4) * 4096
                            + (long)(ti * 16) * 64 + tj * 16;

            const int tx = tid & 15;       // 0..15
            const int ty = tid >> 4;       // 0..15
            const float2* s2v = reinterpret_cast<const float2*>(s2);

            float2 t = s2v[(2 * ty) * 16 + tx];
            float2 u = s2v[(2 * ty + 1) * 16 + tx];

            float LL, LH, HL, HH;
            HAAR(t.x, t.y, u.x, u.y, LL, LH, HL, HH);

            float* orow = o3 + (long)ty * 64 + tx;
            orow[0]         = LL;
            orow[4096]      = LH;
            orow[2 * 4096]  = HL;
            orow[3 * 4096]  = HH;
            s3[ty * 16 + tx] = LL;
        }
        __syncthreads();

        // ---------------- Level 4: s3 -> t4 (8x8 outputs, r/g only) --------
        if (tid < 64 && c < 2) {
            float* o4 = out + S1 + S2 + S3 + (long)b * (12 * 1024)
                            + (long)(c * 4) * 1024
                            + (long)(ti * 8) * 32 + tj * 8;

            const int tx = tid & 7;        // 0..7
            const int ty = tid >> 3;       // 0..7
            const float2* s3v = reinterpret_cast<const float2*>(s3);

            float2 t = s3v[(2 * ty) * 8 + tx];
            float2 u = s3v[(2 * ty + 1) * 8 + tx];

            float LL, LH, HL, HH;
            HAAR(t.x, t.y, u.x, u.y, LL, LH, HL, HH);

            float* orow = o4 + (long)ty * 32 + tx;
            orow[0]         = LL;
            orow[1024]      = LH;
            orow[2 * 1024]  = HL;
            orow[3 * 1024]  = HH;

            if (c == 1) {                  // b4 = g4 -> channels 8..11
                float* orow2 = orow + 4 * 1024;
                orow2[0]         = LL;
                orow2[1024]      = LH;
                orow2[2 * 1024]  = HL;
                orow2[3 * 1024]  = HH;
            }
        }
        __syncthreads();   // s3 (and s1/s2) safe to overwrite next iteration
    }
}

extern "C" void kernel_launch(void* const* d_in, const int* in_sizes, int n_in,
                              void* d_out, int out_size)
{
    const float* x = (const float*)d_in[0];
    float* out = (float*)d_out;

    dim3 block(256, 1, 1);
    dim3 grid(4, 2, 96);   // 768 blocks, 2 row-tiles per block -> single wave
    dwt_fused_kernel<<<grid, block>>>(x, out);
}